// round 1
// baseline (speedup 1.0000x reference)
#include <cuda_runtime.h>
#include <math.h>

#define D        64
#define NU       50000
#define NB       20000
#define NI       100000
#define N_UB     (NU + NB)
#define N_UI     (NU + NI)
#define N_BI     (NB + NI)
#define MAXDEG   50
#define BATCH    2048
#define NCAND    2
#define CORE_K   3

// ---------------- scratch (allocation-free rule: device globals) ----------------
__device__ float g_f[(size_t)N_UI * D];        // working feature buffer (max graph)
__device__ float g_y[(size_t)N_UI * D];        // working feature buffer
__device__ float g_repUB[(size_t)N_UB * D];    // propagated reps (acc)
__device__ float g_repUI[(size_t)N_UI * D];
__device__ float g_repBI[(size_t)N_BI * D];
__device__ float g_scores[BATCH * NCAND];

// ---------------- kernels ----------------

// f = concat(fa, fb); rep = f; y = 0
__global__ void init_kernel(const float* __restrict__ fa, int na64, int ntot64,
                            float* __restrict__ f, float* __restrict__ rep,
                            float* __restrict__ y, const float* __restrict__ fb) {
    int i = blockIdx.x * blockDim.x + threadIdx.x;
    if (i >= ntot64) return;
    float v = (i < na64) ? fa[i] : fb[i - na64];
    f[i] = v;
    rep[i] = v;
    y[i] = 0.f;
}

// y[row] += val * x[col]   (COO scatter, 16 threads per edge, float4 vector atomics)
__global__ void spmm_kernel(const int* __restrict__ row, const int* __restrict__ col,
                            const float* __restrict__ val, const float* __restrict__ x,
                            float* __restrict__ y, int E) {
    int t = blockIdx.x * blockDim.x + threadIdx.x;
    int e = t >> 4;
    if (e >= E) return;
    int l = t & 15;
    float v = __ldg(val + e);
    int r = __ldg(row + e);
    int c = __ldg(col + e);
    const float4 xv = __ldg(reinterpret_cast<const float4*>(x) + (size_t)c * 16 + l);
    float4 o = make_float4(v * xv.x, v * xv.y, v * xv.z, v * xv.w);
    atomicAdd(reinterpret_cast<float4*>(y) + (size_t)r * 16 + l, o);
}

// rep += y; fz = 0 (prepare next layer's output buffer)
__global__ void accum_zero_kernel(float* __restrict__ rep, const float* __restrict__ y,
                                  float* __restrict__ fz, int n) {
    int i = blockIdx.x * blockDim.x + threadIdx.x;
    if (i >= n) return;
    rep[i] += y[i];
    fz[i] = 0.f;
}

// rep = (rep + y) / 3
__global__ void finalize_kernel(float* __restrict__ rep, const float* __restrict__ y, int n) {
    int i = blockIdx.x * blockDim.x + threadIdx.x;
    if (i >= n) return;
    rep[i] = (rep[i] + y[i]) * (1.0f / 3.0f);
}

// One block per (user, bundle) pair.
__global__ void __launch_bounds__(128, 8)
score_kernel(const int* __restrict__ users, const int* __restrict__ bundles,
             const int* __restrict__ bundle_items,
             const float* __restrict__ repUB,   // [N_UB, D]: UB_u then UB_b
             const float* __restrict__ repUI,   // [N_UI, D]: UI_u then UI_i
             const float* __restrict__ repBI,   // [N_BI, D]: BI_b then BI_i
             const float* __restrict__ cw1, const float* __restrict__ cb1,
             const float* __restrict__ cw2, const float* __restrict__ cb2,
             const float* __restrict__ sw1, const float* __restrict__ sb1,
             const float* __restrict__ sw2, const float* __restrict__ sb2,
             float* __restrict__ scores) {
    __shared__ float s_u[D];        // UI_u[user]
    __shared__ float s_ubu[D];      // UB_u[user]
    __shared__ float s_ubb[D];      // UB_b[bundle]
    __shared__ float s_bbi[D];      // BI_b[bundle]
    __shared__ int   s_idx[MAXDEG];
    __shared__ float s_it[MAXDEG * 65];   // items_ui, pitch 65 (bank-conflict-free)
    __shared__ float s_rUI[MAXDEG];
    __shared__ float s_rBI[MAXDEG];
    __shared__ float s_pi[MAXDEG];
    __shared__ float s_cw1[64];
    __shared__ float s_cb1[32];
    __shared__ float s_cw2[32];
    __shared__ float s_cb2v;
    __shared__ float s_max, s_sum, s_cnt;
    __shared__ int   s_topi[CORE_K];
    __shared__ float s_topp[CORE_K];
    __shared__ unsigned char s_fringe[MAXDEG];
    __shared__ float s_core[D], s_fr[D], s_h1[D], s_hat[D];
    __shared__ float s_red[4];

    const int pair = blockIdx.x;
    const int b = pair / NCAND;
    const int tid = threadIdx.x;
    const int user = users[b];
    const int bun  = bundles[pair];

    const float* UI_u = repUI;
    const float* UI_i = repUI + (size_t)NU * D;
    const float* UB_u = repUB;
    const float* UB_b = repUB + (size_t)NU * D;
    const float* BI_b = repBI;
    const float* BI_i = repBI + (size_t)NB * D;

    if (tid < D) {
        s_u[tid]   = UI_u[(size_t)user * D + tid];
        s_ubu[tid] = UB_u[(size_t)user * D + tid];
        s_ubb[tid] = UB_b[(size_t)bun * D + tid];
        s_bbi[tid] = BI_b[(size_t)bun * D + tid];
        s_cw1[tid] = cw1[tid];
    }
    if (tid < MAXDEG) s_idx[tid] = bundle_items[(size_t)bun * MAXDEG + tid];
    if (tid < 32) { s_cb1[tid] = cb1[tid]; s_cw2[tid] = cw2[tid]; }
    if (tid == 0) s_cb2v = cb2[0];
    __syncthreads();

    // cache items_ui tile (zero row for PAD index NI)
    for (int i = tid; i < MAXDEG * D; i += blockDim.x) {
        int m = i >> 6, d = i & 63;
        int ci = s_idx[m];
        s_it[m * 65 + d] = (ci < NI) ? UI_i[(size_t)ci * D + d] : 0.f;
    }
    __syncthreads();

    // r_UI, r_BI: one warp per item
    const int w = tid >> 5, l = tid & 31;
    for (int m = w; m < MAXDEG; m += 4) {
        float a = s_it[m * 65 + l] * s_u[l] + s_it[m * 65 + 32 + l] * s_u[32 + l];
        #pragma unroll
        for (int o = 16; o; o >>= 1) a += __shfl_down_sync(0xffffffffu, a, o);
        int ci = s_idx[m];
        float bs = 0.f;
        if (ci < NI) {
            bs = BI_i[(size_t)ci * D + l] * s_bbi[l]
               + BI_i[(size_t)ci * D + 32 + l] * s_bbi[32 + l];
        }
        #pragma unroll
        for (int o = 16; o; o >>= 1) bs += __shfl_down_sync(0xffffffffu, bs, o);
        if (l == 0) { s_rUI[m] = a; s_rBI[m] = bs; }
    }
    __syncthreads();

    // core MLP -> masked logits
    if (tid < MAXDEG) {
        float logit;
        if (s_idx[tid] < NI) {
            float ru = s_rUI[tid], rb = s_rBI[tid];
            float acc = s_cb2v;
            #pragma unroll
            for (int j = 0; j < 32; j++) {
                float h = fmaf(ru, s_cw1[j], fmaf(rb, s_cw1[32 + j], s_cb1[j]));
                h = fmaxf(h, 0.f);
                acc = fmaf(h, s_cw2[j], acc);
            }
            logit = acc;
        } else {
            logit = -INFINITY;
        }
        s_pi[tid] = logit;
    }
    __syncthreads();
    if (tid == 0) {
        float mx = -INFINITY;
        for (int m = 0; m < MAXDEG; m++) mx = fmaxf(mx, s_pi[m]);
        s_max = mx;
    }
    __syncthreads();
    if (tid < MAXDEG) s_pi[tid] = expf(s_pi[tid] - s_max);
    __syncthreads();
    if (tid == 0) {
        float sum = 0.f;
        for (int m = 0; m < MAXDEG; m++) sum += s_pi[m];
        s_sum = sum;
    }
    __syncthreads();
    if (tid < MAXDEG) s_pi[tid] /= s_sum;
    __syncthreads();

    // top-3 (ties -> lowest index, matching lax.top_k), fringe flags, count
    if (tid == 0) {
        bool taken[MAXDEG];
        for (int m = 0; m < MAXDEG; m++) taken[m] = false;
        float tsum = 0.f;
        #pragma unroll
        for (int k = 0; k < CORE_K; k++) {
            float best = -1.f; int bi = 0;
            for (int m = 0; m < MAXDEG; m++)
                if (!taken[m] && s_pi[m] > best) { best = s_pi[m]; bi = m; }
            taken[bi] = true;
            s_topi[k] = bi;
            s_topp[k] = best;
            tsum += best;
        }
        tsum += 1e-10f;
        #pragma unroll
        for (int k = 0; k < CORE_K; k++) s_topp[k] /= tsum;
        int cnt = 0;
        for (int m = 0; m < MAXDEG; m++) {
            unsigned char fr = (s_idx[m] < NI && !taken[m]) ? 1 : 0;
            s_fringe[m] = fr;
            cnt += fr;
        }
        s_cnt = fmaxf((float)cnt, 1.0f);
    }
    __syncthreads();

    // h_core, h_fringe
    if (tid < D) {
        float hc = 0.f;
        #pragma unroll
        for (int k = 0; k < CORE_K; k++)
            hc = fmaf(s_it[s_topi[k] * 65 + tid], s_topp[k], hc);
        float fs = 0.f;
        for (int m = 0; m < MAXDEG; m++)
            if (s_fringe[m]) fs += s_it[m * 65 + tid];
        s_core[tid] = hc;
        s_fr[tid] = fs / s_cnt;
    }
    __syncthreads();

    // synergy MLP: h1 = relu([core,fringe] @ sw1 + sb1); phi = h1 @ sw2 + sb2
    if (tid < D) {
        float acc = sb1[tid];
        #pragma unroll 8
        for (int i = 0; i < D; i++) acc = fmaf(s_core[i], sw1[i * D + tid], acc);
        #pragma unroll 8
        for (int i = 0; i < D; i++) acc = fmaf(s_fr[i], sw1[(D + i) * D + tid], acc);
        s_h1[tid] = fmaxf(acc, 0.f);
    }
    __syncthreads();
    if (tid < D) {
        float acc = sb2[tid];
        #pragma unroll 8
        for (int j = 0; j < D; j++) acc = fmaf(s_h1[j], sw2[j * D + tid], acc);
        s_hat[tid] = s_core[tid] + acc;
    }
    __syncthreads();

    // score = dot(u_ui, UB_b[bundle]) + dot(UB_u[user], hat_e_BI)
    float part = 0.f;
    if (tid < D) part = s_u[tid] * s_ubb[tid] + s_ubu[tid] * s_hat[tid];
    #pragma unroll
    for (int o = 16; o; o >>= 1) part += __shfl_down_sync(0xffffffffu, part, o);
    if (l == 0) s_red[w] = part;
    __syncthreads();
    if (tid == 0) scores[pair] = s_red[0] + s_red[1] + s_red[2] + s_red[3];
}

// bpr = mean softplus(s[:,1] - s[:,0])
__global__ void loss_kernel(const float* __restrict__ scores, float* __restrict__ out) {
    __shared__ float red[8];
    float acc = 0.f;
    for (int b = threadIdx.x; b < BATCH; b += blockDim.x) {
        float x = scores[b * 2 + 1] - scores[b * 2 + 0];
        float sp = (x > 0.f) ? x + log1pf(expf(-x)) : log1pf(expf(x));
        acc += sp;
    }
    #pragma unroll
    for (int o = 16; o; o >>= 1) acc += __shfl_down_sync(0xffffffffu, acc, o);
    if ((threadIdx.x & 31) == 0) red[threadIdx.x >> 5] = acc;
    __syncthreads();
    if (threadIdx.x == 0) {
        float s = 0.f;
        for (int i = 0; i < 8; i++) s += red[i];
        out[0] = s * (1.0f / BATCH);
    }
}

// ---------------- host ----------------

static void run_graph(const float* fa, int na, const float* fb, int nb,
                      const int* row, const int* col, const float* val, int E,
                      float* f, float* y, float* rep) {
    int n64 = (na + nb) * D;
    int gb = (n64 + 255) / 256;
    int sg = (int)(((long long)E * 16 + 255) / 256);
    init_kernel<<<gb, 256>>>(fa, na * D, n64, f, rep, y, fb);
    spmm_kernel<<<sg, 256>>>(row, col, val, f, y, E);           // layer 1 -> y
    accum_zero_kernel<<<gb, 256>>>(rep, y, f, n64);             // rep += y; f = 0
    spmm_kernel<<<sg, 256>>>(row, col, val, y, f, E);           // layer 2 -> f
    finalize_kernel<<<gb, 256>>>(rep, f, n64);                  // rep = (rep+f)/3
}

extern "C" void kernel_launch(void* const* d_in, const int* in_sizes, int n_in,
                              void* d_out, int out_size) {
    const float* users_feature   = (const float*)d_in[0];
    const float* bundles_feature = (const float*)d_in[1];
    const float* items_feature   = (const float*)d_in[2];
    const float* cw1 = (const float*)d_in[3];
    const float* cb1 = (const float*)d_in[4];
    const float* cw2 = (const float*)d_in[5];
    const float* cb2 = (const float*)d_in[6];
    const float* sw1 = (const float*)d_in[7];
    const float* sb1 = (const float*)d_in[8];
    const float* sw2 = (const float*)d_in[9];
    const float* sb2 = (const float*)d_in[10];
    const float* ub_val = (const float*)d_in[11];
    const float* ui_val = (const float*)d_in[12];
    const float* bi_val = (const float*)d_in[13];
    const int* users   = (const int*)d_in[14];
    const int* bundles = (const int*)d_in[15];
    const int* ub_row = (const int*)d_in[16];
    const int* ub_col = (const int*)d_in[17];
    const int* ui_row = (const int*)d_in[18];
    const int* ui_col = (const int*)d_in[19];
    const int* bi_row = (const int*)d_in[20];
    const int* bi_col = (const int*)d_in[21];
    const int* bundle_items = (const int*)d_in[22];

    int E_UB = in_sizes[11];
    int E_UI = in_sizes[12];
    int E_BI = in_sizes[13];

    float *f, *y, *repUB, *repUI, *repBI, *scores;
    cudaGetSymbolAddress((void**)&f, g_f);
    cudaGetSymbolAddress((void**)&y, g_y);
    cudaGetSymbolAddress((void**)&repUB, g_repUB);
    cudaGetSymbolAddress((void**)&repUI, g_repUI);
    cudaGetSymbolAddress((void**)&repBI, g_repBI);
    cudaGetSymbolAddress((void**)&scores, g_scores);

    run_graph(users_feature, NU, bundles_feature, NB, ub_row, ub_col, ub_val, E_UB, f, y, repUB);
    run_graph(users_feature, NU, items_feature,   NI, ui_row, ui_col, ui_val, E_UI, f, y, repUI);
    run_graph(bundles_feature, NB, items_feature, NI, bi_row, bi_col, bi_val, E_BI, f, y, repBI);

    score_kernel<<<BATCH * NCAND, 128>>>(users, bundles, bundle_items,
                                         repUB, repUI, repBI,
                                         cw1, cb1, cw2, cb2,
                                         sw1, sb1, sw2, sb2, scores);
    loss_kernel<<<1, 256>>>(scores, (float*)d_out);
}

// round 2
// speedup vs baseline: 1.5802x; 1.5802x over previous
#include <cuda_runtime.h>
#include <math.h>

#define D        64
#define NU       50000
#define NB       20000
#define NI       100000
#define N_UB     (NU + NB)
#define N_UI     (NU + NI)
#define N_BI     (NB + NI)
#define MAXDEG   50
#define BATCH    2048
#define NCAND    2
#define CORE_K   3

// ---------------- scratch (allocation-free rule: device globals) ----------------
__device__ float g_y1[(size_t)N_UI * D];       // layer-1 output (max graph size)
__device__ float g_y2[(size_t)N_UI * D];       // layer-2 output
__device__ float g_repUB[(size_t)N_UB * D];    // final propagated reps
__device__ float g_repUI[(size_t)N_UI * D];
__device__ float g_repBI[(size_t)N_BI * D];
__device__ float g_scores[BATCH * NCAND];

// ---------------- kernels ----------------

// zero y1,y2 (float4 vectorized); n4 = n64/4
__global__ void zero2_kernel(float4* __restrict__ y1, float4* __restrict__ y2, int n4) {
    int i = blockIdx.x * blockDim.x + threadIdx.x;
    if (i >= n4) return;
    float4 z = make_float4(0.f, 0.f, 0.f, 0.f);
    y1[i] = z;
    y2[i] = z;
}

// y[row] += val * x[col]; x is the virtual concat [xa; xb] split at row na.
// 16 threads per edge; edge scalars loaded once per half-warp and shfl-broadcast.
__global__ void spmm_kernel(const int* __restrict__ row, const int* __restrict__ col,
                            const float* __restrict__ val,
                            const float* __restrict__ xa, const float* __restrict__ xb,
                            int na, float* __restrict__ y, int E) {
    int t = blockIdx.x * blockDim.x + threadIdx.x;
    int e = t >> 4;
    int l = threadIdx.x & 31;
    int sub = threadIdx.x & 15;
    bool valid = (e < E);
    int r = 0, c = 0; float v = 0.f;
    if (sub == 0 && valid) {
        r = __ldg(row + e);
        c = __ldg(col + e);
        v = __ldg(val + e);
    }
    int src = l & 16;  // broadcast source lane for this half-warp
    r = __shfl_sync(0xffffffffu, r, src);
    c = __shfl_sync(0xffffffffu, c, src);
    v = __shfl_sync(0xffffffffu, v, src);
    if (!valid) return;
    const float4* xr = (c < na)
        ? reinterpret_cast<const float4*>(xa) + (size_t)c * 16
        : reinterpret_cast<const float4*>(xb) + (size_t)(c - na) * 16;
    float4 xv = __ldg(xr + sub);
    float4 o = make_float4(v * xv.x, v * xv.y, v * xv.z, v * xv.w);
    atomicAdd(reinterpret_cast<float4*>(y) + (size_t)r * 16 + sub, o);
}

// rep = (concat(fa,fb) + y1 + y2) / 3   (float4 vectorized)
__global__ void finalize_kernel(const float4* __restrict__ fa, int na4, int ntot4,
                                const float4* __restrict__ fb,
                                const float4* __restrict__ y1,
                                const float4* __restrict__ y2,
                                float4* __restrict__ rep) {
    int i = blockIdx.x * blockDim.x + threadIdx.x;
    if (i >= ntot4) return;
    float4 x0 = (i < na4) ? fa[i] : fb[i - na4];
    float4 a = y1[i], b = y2[i];
    const float s = 1.0f / 3.0f;
    float4 o;
    o.x = (x0.x + a.x + b.x) * s;
    o.y = (x0.y + a.y + b.y) * s;
    o.z = (x0.z + a.z + b.z) * s;
    o.w = (x0.w + a.w + b.w) * s;
    rep[i] = o;
}

// One block per (user, bundle) pair.
__global__ void __launch_bounds__(128, 8)
score_kernel(const int* __restrict__ users, const int* __restrict__ bundles,
             const int* __restrict__ bundle_items,
             const float* __restrict__ repUB,   // [N_UB, D]: UB_u then UB_b
             const float* __restrict__ repUI,   // [N_UI, D]: UI_u then UI_i
             const float* __restrict__ repBI,   // [N_BI, D]: BI_b then BI_i
             const float* __restrict__ cw1, const float* __restrict__ cb1,
             const float* __restrict__ cw2, const float* __restrict__ cb2,
             const float* __restrict__ sw1, const float* __restrict__ sb1,
             const float* __restrict__ sw2, const float* __restrict__ sb2,
             float* __restrict__ scores) {
    __shared__ float s_u[D];        // UI_u[user]
    __shared__ float s_ubu[D];      // UB_u[user]
    __shared__ float s_ubb[D];      // UB_b[bundle]
    __shared__ float s_bbi[D];      // BI_b[bundle]
    __shared__ int   s_idx[MAXDEG];
    __shared__ float s_it[MAXDEG * 65];   // items_ui, pitch 65 (bank-conflict-free)
    __shared__ float s_rUI[MAXDEG];
    __shared__ float s_rBI[MAXDEG];
    __shared__ float s_pi[MAXDEG];
    __shared__ float s_cw1[64];
    __shared__ float s_cb1[32];
    __shared__ float s_cw2[32];
    __shared__ float s_cb2v;
    __shared__ float s_max, s_sum, s_cnt;
    __shared__ int   s_topi[CORE_K];
    __shared__ float s_topp[CORE_K];
    __shared__ unsigned char s_fringe[MAXDEG];
    __shared__ float s_core[D], s_fr[D], s_h1[D], s_hat[D];
    __shared__ float s_red[4];

    const int pair = blockIdx.x;
    const int b = pair / NCAND;
    const int tid = threadIdx.x;
    const int user = users[b];
    const int bun  = bundles[pair];

    const float* UI_u = repUI;
    const float* UI_i = repUI + (size_t)NU * D;
    const float* UB_u = repUB;
    const float* UB_b = repUB + (size_t)NU * D;
    const float* BI_b = repBI;
    const float* BI_i = repBI + (size_t)NB * D;

    if (tid < D) {
        s_u[tid]   = UI_u[(size_t)user * D + tid];
        s_ubu[tid] = UB_u[(size_t)user * D + tid];
        s_ubb[tid] = UB_b[(size_t)bun * D + tid];
        s_bbi[tid] = BI_b[(size_t)bun * D + tid];
        s_cw1[tid] = cw1[tid];
    }
    if (tid < MAXDEG) s_idx[tid] = bundle_items[(size_t)bun * MAXDEG + tid];
    if (tid < 32) { s_cb1[tid] = cb1[tid]; s_cw2[tid] = cw2[tid]; }
    if (tid == 0) s_cb2v = cb2[0];
    __syncthreads();

    // cache items_ui tile (zero row for PAD index NI)
    for (int i = tid; i < MAXDEG * D; i += blockDim.x) {
        int m = i >> 6, d = i & 63;
        int ci = s_idx[m];
        s_it[m * 65 + d] = (ci < NI) ? UI_i[(size_t)ci * D + d] : 0.f;
    }
    __syncthreads();

    // r_UI, r_BI: one warp per item
    const int w = tid >> 5, l = tid & 31;
    for (int m = w; m < MAXDEG; m += 4) {
        float a = s_it[m * 65 + l] * s_u[l] + s_it[m * 65 + 32 + l] * s_u[32 + l];
        #pragma unroll
        for (int o = 16; o; o >>= 1) a += __shfl_down_sync(0xffffffffu, a, o);
        int ci = s_idx[m];
        float bs = 0.f;
        if (ci < NI) {
            bs = BI_i[(size_t)ci * D + l] * s_bbi[l]
               + BI_i[(size_t)ci * D + 32 + l] * s_bbi[32 + l];
        }
        #pragma unroll
        for (int o = 16; o; o >>= 1) bs += __shfl_down_sync(0xffffffffu, bs, o);
        if (l == 0) { s_rUI[m] = a; s_rBI[m] = bs; }
    }
    __syncthreads();

    // core MLP -> masked logits
    if (tid < MAXDEG) {
        float logit;
        if (s_idx[tid] < NI) {
            float ru = s_rUI[tid], rb = s_rBI[tid];
            float acc = s_cb2v;
            #pragma unroll
            for (int j = 0; j < 32; j++) {
                float h = fmaf(ru, s_cw1[j], fmaf(rb, s_cw1[32 + j], s_cb1[j]));
                h = fmaxf(h, 0.f);
                acc = fmaf(h, s_cw2[j], acc);
            }
            logit = acc;
        } else {
            logit = -INFINITY;
        }
        s_pi[tid] = logit;
    }
    __syncthreads();
    if (tid == 0) {
        float mx = -INFINITY;
        for (int m = 0; m < MAXDEG; m++) mx = fmaxf(mx, s_pi[m]);
        s_max = mx;
    }
    __syncthreads();
    if (tid < MAXDEG) s_pi[tid] = expf(s_pi[tid] - s_max);
    __syncthreads();
    if (tid == 0) {
        float sum = 0.f;
        for (int m = 0; m < MAXDEG; m++) sum += s_pi[m];
        s_sum = sum;
    }
    __syncthreads();
    if (tid < MAXDEG) s_pi[tid] /= s_sum;
    __syncthreads();

    // top-3 (ties -> lowest index, matching lax.top_k), fringe flags, count
    if (tid == 0) {
        bool taken[MAXDEG];
        for (int m = 0; m < MAXDEG; m++) taken[m] = false;
        float tsum = 0.f;
        #pragma unroll
        for (int k = 0; k < CORE_K; k++) {
            float best = -1.f; int bi = 0;
            for (int m = 0; m < MAXDEG; m++)
                if (!taken[m] && s_pi[m] > best) { best = s_pi[m]; bi = m; }
            taken[bi] = true;
            s_topi[k] = bi;
            s_topp[k] = best;
            tsum += best;
        }
        tsum += 1e-10f;
        #pragma unroll
        for (int k = 0; k < CORE_K; k++) s_topp[k] /= tsum;
        int cnt = 0;
        for (int m = 0; m < MAXDEG; m++) {
            unsigned char fr = (s_idx[m] < NI && !taken[m]) ? 1 : 0;
            s_fringe[m] = fr;
            cnt += fr;
        }
        s_cnt = fmaxf((float)cnt, 1.0f);
    }
    __syncthreads();

    // h_core, h_fringe
    if (tid < D) {
        float hc = 0.f;
        #pragma unroll
        for (int k = 0; k < CORE_K; k++)
            hc = fmaf(s_it[s_topi[k] * 65 + tid], s_topp[k], hc);
        float fs = 0.f;
        for (int m = 0; m < MAXDEG; m++)
            if (s_fringe[m]) fs += s_it[m * 65 + tid];
        s_core[tid] = hc;
        s_fr[tid] = fs / s_cnt;
    }
    __syncthreads();

    // synergy MLP: h1 = relu([core,fringe] @ sw1 + sb1); phi = h1 @ sw2 + sb2
    if (tid < D) {
        float acc = sb1[tid];
        #pragma unroll 8
        for (int i = 0; i < D; i++) acc = fmaf(s_core[i], sw1[i * D + tid], acc);
        #pragma unroll 8
        for (int i = 0; i < D; i++) acc = fmaf(s_fr[i], sw1[(D + i) * D + tid], acc);
        s_h1[tid] = fmaxf(acc, 0.f);
    }
    __syncthreads();
    if (tid < D) {
        float acc = sb2[tid];
        #pragma unroll 8
        for (int j = 0; j < D; j++) acc = fmaf(s_h1[j], sw2[j * D + tid], acc);
        s_hat[tid] = s_core[tid] + acc;
    }
    __syncthreads();

    // score = dot(u_ui, UB_b[bundle]) + dot(UB_u[user], hat_e_BI)
    float part = 0.f;
    if (tid < D) part = s_u[tid] * s_ubb[tid] + s_ubu[tid] * s_hat[tid];
    #pragma unroll
    for (int o = 16; o; o >>= 1) part += __shfl_down_sync(0xffffffffu, part, o);
    if (l == 0) s_red[w] = part;
    __syncthreads();
    if (tid == 0) scores[pair] = s_red[0] + s_red[1] + s_red[2] + s_red[3];
}

// bpr = mean softplus(s[:,1] - s[:,0])
__global__ void loss_kernel(const float* __restrict__ scores, float* __restrict__ out) {
    __shared__ float red[8];
    float acc = 0.f;
    for (int b = threadIdx.x; b < BATCH; b += blockDim.x) {
        float x = scores[b * 2 + 1] - scores[b * 2 + 0];
        float sp = (x > 0.f) ? x + log1pf(expf(-x)) : log1pf(expf(x));
        acc += sp;
    }
    #pragma unroll
    for (int o = 16; o; o >>= 1) acc += __shfl_down_sync(0xffffffffu, acc, o);
    if ((threadIdx.x & 31) == 0) red[threadIdx.x >> 5] = acc;
    __syncthreads();
    if (threadIdx.x == 0) {
        float s = 0.f;
        for (int i = 0; i < 8; i++) s += red[i];
        out[0] = s * (1.0f / BATCH);
    }
}

// ---------------- host ----------------

static void run_graph(const float* fa, int na, const float* fb, int nb,
                      const int* row, const int* col, const float* val, int E,
                      float* y1, float* y2, float* rep) {
    int ntot = na + nb;
    int n4 = ntot * (D / 4);
    int gz = (n4 + 255) / 256;
    int sg = (int)(((long long)E * 16 + 255) / 256);
    zero2_kernel<<<gz, 256>>>((float4*)y1, (float4*)y2, n4);
    // layer 1: gather from virtual concat(fa,fb) -> y1
    spmm_kernel<<<sg, 256>>>(row, col, val, fa, fb, na, y1, E);
    // layer 2: gather from y1 -> y2 (na=ntot so branch always takes xa)
    spmm_kernel<<<sg, 256>>>(row, col, val, y1, y1, ntot, y2, E);
    // rep = (x0 + y1 + y2) / 3
    finalize_kernel<<<gz, 256>>>((const float4*)fa, na * (D / 4), n4,
                                 (const float4*)fb, (const float4*)y1,
                                 (const float4*)y2, (float4*)rep);
}

extern "C" void kernel_launch(void* const* d_in, const int* in_sizes, int n_in,
                              void* d_out, int out_size) {
    const float* users_feature   = (const float*)d_in[0];
    const float* bundles_feature = (const float*)d_in[1];
    const float* items_feature   = (const float*)d_in[2];
    const float* cw1 = (const float*)d_in[3];
    const float* cb1 = (const float*)d_in[4];
    const float* cw2 = (const float*)d_in[5];
    const float* cb2 = (const float*)d_in[6];
    const float* sw1 = (const float*)d_in[7];
    const float* sb1 = (const float*)d_in[8];
    const float* sw2 = (const float*)d_in[9];
    const float* sb2 = (const float*)d_in[10];
    const float* ub_val = (const float*)d_in[11];
    const float* ui_val = (const float*)d_in[12];
    const float* bi_val = (const float*)d_in[13];
    const int* users   = (const int*)d_in[14];
    const int* bundles = (const int*)d_in[15];
    const int* ub_row = (const int*)d_in[16];
    const int* ub_col = (const int*)d_in[17];
    const int* ui_row = (const int*)d_in[18];
    const int* ui_col = (const int*)d_in[19];
    const int* bi_row = (const int*)d_in[20];
    const int* bi_col = (const int*)d_in[21];
    const int* bundle_items = (const int*)d_in[22];

    int E_UB = in_sizes[11];
    int E_UI = in_sizes[12];
    int E_BI = in_sizes[13];

    float *y1, *y2, *repUB, *repUI, *repBI, *scores;
    cudaGetSymbolAddress((void**)&y1, g_y1);
    cudaGetSymbolAddress((void**)&y2, g_y2);
    cudaGetSymbolAddress((void**)&repUB, g_repUB);
    cudaGetSymbolAddress((void**)&repUI, g_repUI);
    cudaGetSymbolAddress((void**)&repBI, g_repBI);
    cudaGetSymbolAddress((void**)&scores, g_scores);

    run_graph(users_feature, NU, bundles_feature, NB, ub_row, ub_col, ub_val, E_UB, y1, y2, repUB);
    run_graph(users_feature, NU, items_feature,   NI, ui_row, ui_col, ui_val, E_UI, y1, y2, repUI);
    run_graph(bundles_feature, NB, items_feature, NI, bi_row, bi_col, bi_val, E_BI, y1, y2, repBI);

    score_kernel<<<BATCH * NCAND, 128>>>(users, bundles, bundle_items,
                                         repUB, repUI, repBI,
                                         cw1, cb1, cw2, cb2,
                                         sw1, sb1, sw2, sb2, scores);
    loss_kernel<<<1, 256>>>(scores, (float*)d_out);
}

// round 4
// speedup vs baseline: 2.0946x; 1.3255x over previous
#include <cuda_runtime.h>
#include <math.h>

#define D        64
#define NU       50000
#define NB       20000
#define NI       100000
#define N_UB     (NU + NB)
#define N_UI     (NU + NI)
#define N_BI     (NB + NI)
#define MAXDEG   50
#define BATCH    2048
#define NCAND    2
#define CORE_K   3
#define EMAX     1200000

// ---------------- scratch (allocation-free rule: device globals) ----------------
__device__ float g_y1[(size_t)N_UI * D];       // layer-1 output (max graph size)
__device__ float g_repUB[(size_t)N_UB * D];    // final propagated reps
__device__ float g_repUI[(size_t)N_UI * D];
__device__ float g_repBI[(size_t)N_BI * D];
__device__ int   g_cnt[N_UI];                  // counts -> partial scan -> cursor
__device__ int   g_rowptr[N_UI + 1];
__device__ int   g_part[256];
__device__ int   g_ccol[EMAX];
__device__ float g_cval[EMAX];
__device__ float g_scores[BATCH * NCAND];

// ---------------- CSR build ----------------

__global__ void zero_int_kernel(int* __restrict__ p, int n) {
    int i = blockIdx.x * blockDim.x + threadIdx.x;
    if (i < n) p[i] = 0;
}

__global__ void hist_kernel(const int* __restrict__ row, int* __restrict__ cnt, int E) {
    int e = blockIdx.x * blockDim.x + threadIdx.x;
    if (e < E) atomicAdd(&cnt[__ldg(row + e)], 1);
}

// block-local exclusive scan over 1024-element tiles (256 thr x 4); data updated in place,
// per-block totals to part[]
__global__ void scan1_kernel(int* __restrict__ data, int* __restrict__ part, int n) {
    __shared__ int sh[256];
    int tid = threadIdx.x;
    int base = blockIdx.x * 1024 + tid * 4;
    int v0 = 0, v1 = 0, v2 = 0, v3 = 0;
    if (base + 0 < n) v0 = data[base + 0];
    if (base + 1 < n) v1 = data[base + 1];
    if (base + 2 < n) v2 = data[base + 2];
    if (base + 3 < n) v3 = data[base + 3];
    int s = v0 + v1 + v2 + v3;
    sh[tid] = s;
    __syncthreads();
    #pragma unroll
    for (int off = 1; off < 256; off <<= 1) {
        int t = (tid >= off) ? sh[tid - off] : 0;
        __syncthreads();
        sh[tid] += t;
        __syncthreads();
    }
    if (tid == 255) part[blockIdx.x] = sh[255];
    int run = sh[tid] - s;  // exclusive
    if (base + 0 < n) { data[base + 0] = run; run += v0; }
    if (base + 1 < n) { data[base + 1] = run; run += v1; }
    if (base + 2 < n) { data[base + 2] = run; run += v2; }
    if (base + 3 < n) { data[base + 3] = run; run += v3; }
}

// exclusive scan of part[np] (np <= 256), single block
__global__ void scan2_kernel(int* __restrict__ part, int np) {
    __shared__ int sh[256];
    int tid = threadIdx.x;
    int s = (tid < np) ? part[tid] : 0;
    sh[tid] = s;
    __syncthreads();
    #pragma unroll
    for (int off = 1; off < 256; off <<= 1) {
        int t = (tid >= off) ? sh[tid - off] : 0;
        __syncthreads();
        sh[tid] += t;
        __syncthreads();
    }
    if (tid < np) part[tid] = sh[tid] - s;
}

// rowptr[i] = data[i] + part[i/1024]; data becomes cursor; rowptr[n] = E
__global__ void scan3_kernel(int* __restrict__ data, const int* __restrict__ part,
                             int* __restrict__ rowptr, int n, int E) {
    int i = blockIdx.x * blockDim.x + threadIdx.x;
    if (i < n) {
        int v = data[i] + part[i >> 10];
        rowptr[i] = v;
        data[i] = v;   // cursor
    }
    if (i == 0) rowptr[n] = E;
}

__global__ void scatter_kernel(const int* __restrict__ row, const int* __restrict__ col,
                               const float* __restrict__ val, int* __restrict__ cursor,
                               int* __restrict__ ccol, float* __restrict__ cval, int E) {
    int e = blockIdx.x * blockDim.x + threadIdx.x;
    if (e >= E) return;
    int r = __ldg(row + e);
    int p = atomicAdd(&cursor[r], 1);
    ccol[p] = __ldg(col + e);
    cval[p] = __ldg(val + e);
}

// ---------------- gather spmm (half-warp per row) ----------------
// gather source is virtual concat [xa; xb] split at row na.
// FIN: out = (x0 + yprev + acc)/3 with x0 = concat(x0a,x0b) split at na0; else out = acc.
template <bool FIN>
__global__ void __launch_bounds__(256)
spmm_csr_kernel(const int* __restrict__ rowptr, const int* __restrict__ ccol,
                const float* __restrict__ cval,
                const float* __restrict__ xa, const float* __restrict__ xb, int na,
                const float* __restrict__ x0a, const float* __restrict__ x0b, int na0,
                const float* __restrict__ yprev, float* __restrict__ out, int nrows) {
    int g = blockIdx.x * blockDim.x + threadIdx.x;
    int r = g >> 4;
    if (r >= nrows) return;
    int lane = threadIdx.x & 31;
    int sub = lane & 15;
    unsigned mask = (lane < 16) ? 0x0000FFFFu : 0xFFFF0000u;
    int beg = __ldg(rowptr + r), end = __ldg(rowptr + r + 1);
    float4 acc = make_float4(0.f, 0.f, 0.f, 0.f);
    for (int e0 = beg; e0 < end; e0 += 16) {
        int idx = e0 + sub;
        int c = 0; float v = 0.f;
        if (idx < end) { c = __ldg(ccol + idx); v = __ldg(cval + idx); }
        int cnt = end - e0; if (cnt > 16) cnt = 16;
        for (int j = 0; j < cnt; j++) {
            int cj = __shfl_sync(mask, c, j, 16);
            float vj = __shfl_sync(mask, v, j, 16);
            const float4* xr = (cj < na)
                ? reinterpret_cast<const float4*>(xa) + (size_t)cj * 16
                : reinterpret_cast<const float4*>(xb) + (size_t)(cj - na) * 16;
            float4 xv = __ldg(xr + sub);
            acc.x = fmaf(vj, xv.x, acc.x);
            acc.y = fmaf(vj, xv.y, acc.y);
            acc.z = fmaf(vj, xv.z, acc.z);
            acc.w = fmaf(vj, xv.w, acc.w);
        }
    }
    size_t o = (size_t)r * 16 + sub;
    if (FIN) {
        float4 x0 = (r < na0)
            ? __ldg(reinterpret_cast<const float4*>(x0a) + (size_t)r * 16 + sub)
            : __ldg(reinterpret_cast<const float4*>(x0b) + (size_t)(r - na0) * 16 + sub);
        float4 y1v = __ldg(reinterpret_cast<const float4*>(yprev) + o);
        const float s = 1.0f / 3.0f;
        acc.x = (acc.x + x0.x + y1v.x) * s;
        acc.y = (acc.y + x0.y + y1v.y) * s;
        acc.z = (acc.z + x0.z + y1v.z) * s;
        acc.w = (acc.w + x0.w + y1v.w) * s;
    }
    reinterpret_cast<float4*>(out)[o] = acc;
}

// ---------------- scoring ----------------

// One block per (user, bundle) pair.
__global__ void __launch_bounds__(128, 8)
score_kernel(const int* __restrict__ users, const int* __restrict__ bundles,
             const int* __restrict__ bundle_items,
             const float* __restrict__ repUB,   // [N_UB, D]: UB_u then UB_b
             const float* __restrict__ repUI,   // [N_UI, D]: UI_u then UI_i
             const float* __restrict__ repBI,   // [N_BI, D]: BI_b then BI_i
             const float* __restrict__ cw1, const float* __restrict__ cb1,
             const float* __restrict__ cw2, const float* __restrict__ cb2,
             const float* __restrict__ sw1, const float* __restrict__ sb1,
             const float* __restrict__ sw2, const float* __restrict__ sb2,
             float* __restrict__ scores) {
    __shared__ float s_u[D];        // UI_u[user]
    __shared__ float s_ubu[D];      // UB_u[user]
    __shared__ float s_ubb[D];      // UB_b[bundle]
    __shared__ float s_bbi[D];      // BI_b[bundle]
    __shared__ int   s_idx[MAXDEG];
    __shared__ float s_it[MAXDEG * 65];   // items_ui, pitch 65 (bank-conflict-free)
    __shared__ float s_rUI[MAXDEG];
    __shared__ float s_rBI[MAXDEG];
    __shared__ float s_pi[MAXDEG];
    __shared__ float s_cw1[64];
    __shared__ float s_cb1[32];
    __shared__ float s_cw2[32];
    __shared__ float s_cb2v;
    __shared__ float s_max, s_sum, s_cnt;
    __shared__ int   s_topi[CORE_K];
    __shared__ float s_topp[CORE_K];
    __shared__ unsigned char s_fringe[MAXDEG];
    __shared__ float s_core[D], s_fr[D], s_h1[D], s_hat[D];
    __shared__ float s_red[4];

    const int pair = blockIdx.x;
    const int b = pair / NCAND;
    const int tid = threadIdx.x;
    const int user = users[b];
    const int bun  = bundles[pair];

    const float* UI_u = repUI;
    const float* UI_i = repUI + (size_t)NU * D;
    const float* UB_u = repUB;
    const float* UB_b = repUB + (size_t)NU * D;
    const float* BI_b = repBI;
    const float* BI_i = repBI + (size_t)NB * D;

    if (tid < D) {
        s_u[tid]   = UI_u[(size_t)user * D + tid];
        s_ubu[tid] = UB_u[(size_t)user * D + tid];
        s_ubb[tid] = UB_b[(size_t)bun * D + tid];
        s_bbi[tid] = BI_b[(size_t)bun * D + tid];
        s_cw1[tid] = cw1[tid];
    }
    if (tid < MAXDEG) s_idx[tid] = bundle_items[(size_t)bun * MAXDEG + tid];
    if (tid < 32) { s_cb1[tid] = cb1[tid]; s_cw2[tid] = cw2[tid]; }
    if (tid == 0) s_cb2v = cb2[0];
    __syncthreads();

    // cache items_ui tile (zero row for PAD index NI)
    for (int i = tid; i < MAXDEG * D; i += blockDim.x) {
        int m = i >> 6, d = i & 63;
        int ci = s_idx[m];
        s_it[m * 65 + d] = (ci < NI) ? UI_i[(size_t)ci * D + d] : 0.f;
    }
    __syncthreads();

    // r_UI, r_BI: one warp per item
    const int w = tid >> 5, l = tid & 31;
    for (int m = w; m < MAXDEG; m += 4) {
        float a = s_it[m * 65 + l] * s_u[l] + s_it[m * 65 + 32 + l] * s_u[32 + l];
        #pragma unroll
        for (int o = 16; o; o >>= 1) a += __shfl_down_sync(0xffffffffu, a, o);
        int ci = s_idx[m];
        float bs = 0.f;
        if (ci < NI) {
            bs = BI_i[(size_t)ci * D + l] * s_bbi[l]
               + BI_i[(size_t)ci * D + 32 + l] * s_bbi[32 + l];
        }
        #pragma unroll
        for (int o = 16; o; o >>= 1) bs += __shfl_down_sync(0xffffffffu, bs, o);
        if (l == 0) { s_rUI[m] = a; s_rBI[m] = bs; }
    }
    __syncthreads();

    // core MLP -> masked logits
    if (tid < MAXDEG) {
        float logit;
        if (s_idx[tid] < NI) {
            float ru = s_rUI[tid], rb = s_rBI[tid];
            float acc = s_cb2v;
            #pragma unroll
            for (int j = 0; j < 32; j++) {
                float h = fmaf(ru, s_cw1[j], fmaf(rb, s_cw1[32 + j], s_cb1[j]));
                h = fmaxf(h, 0.f);
                acc = fmaf(h, s_cw2[j], acc);
            }
            logit = acc;
        } else {
            logit = -INFINITY;
        }
        s_pi[tid] = logit;
    }
    __syncthreads();
    if (tid == 0) {
        float mx = -INFINITY;
        for (int m = 0; m < MAXDEG; m++) mx = fmaxf(mx, s_pi[m]);
        s_max = mx;
    }
    __syncthreads();
    if (tid < MAXDEG) s_pi[tid] = expf(s_pi[tid] - s_max);
    __syncthreads();
    if (tid == 0) {
        float sum = 0.f;
        for (int m = 0; m < MAXDEG; m++) sum += s_pi[m];
        s_sum = sum;
    }
    __syncthreads();
    if (tid < MAXDEG) s_pi[tid] /= s_sum;
    __syncthreads();

    // top-3 (ties -> lowest index, matching lax.top_k), fringe flags, count
    if (tid == 0) {
        bool taken[MAXDEG];
        for (int m = 0; m < MAXDEG; m++) taken[m] = false;
        float tsum = 0.f;
        #pragma unroll
        for (int k = 0; k < CORE_K; k++) {
            float best = -1.f; int bi = 0;
            for (int m = 0; m < MAXDEG; m++)
                if (!taken[m] && s_pi[m] > best) { best = s_pi[m]; bi = m; }
            taken[bi] = true;
            s_topi[k] = bi;
            s_topp[k] = best;
            tsum += best;
        }
        tsum += 1e-10f;
        #pragma unroll
        for (int k = 0; k < CORE_K; k++) s_topp[k] /= tsum;
        int cnt = 0;
        for (int m = 0; m < MAXDEG; m++) {
            unsigned char fr = (s_idx[m] < NI && !taken[m]) ? 1 : 0;
            s_fringe[m] = fr;
            cnt += fr;
        }
        s_cnt = fmaxf((float)cnt, 1.0f);
    }
    __syncthreads();

    // h_core, h_fringe
    if (tid < D) {
        float hc = 0.f;
        #pragma unroll
        for (int k = 0; k < CORE_K; k++)
            hc = fmaf(s_it[s_topi[k] * 65 + tid], s_topp[k], hc);
        float fs = 0.f;
        for (int m = 0; m < MAXDEG; m++)
            if (s_fringe[m]) fs += s_it[m * 65 + tid];
        s_core[tid] = hc;
        s_fr[tid] = fs / s_cnt;
    }
    __syncthreads();

    // synergy MLP: h1 = relu([core,fringe] @ sw1 + sb1); phi = h1 @ sw2 + sb2
    if (tid < D) {
        float acc = sb1[tid];
        #pragma unroll 8
        for (int i = 0; i < D; i++) acc = fmaf(s_core[i], sw1[i * D + tid], acc);
        #pragma unroll 8
        for (int i = 0; i < D; i++) acc = fmaf(s_fr[i], sw1[(D + i) * D + tid], acc);
        s_h1[tid] = fmaxf(acc, 0.f);
    }
    __syncthreads();
    if (tid < D) {
        float acc = sb2[tid];
        #pragma unroll 8
        for (int j = 0; j < D; j++) acc = fmaf(s_h1[j], sw2[j * D + tid], acc);
        s_hat[tid] = s_core[tid] + acc;
    }
    __syncthreads();

    // score = dot(u_ui, UB_b[bundle]) + dot(UB_u[user], hat_e_BI)
    float part = 0.f;
    if (tid < D) part = s_u[tid] * s_ubb[tid] + s_ubu[tid] * s_hat[tid];
    #pragma unroll
    for (int o = 16; o; o >>= 1) part += __shfl_down_sync(0xffffffffu, part, o);
    if (l == 0) s_red[w] = part;
    __syncthreads();
    if (tid == 0) scores[pair] = s_red[0] + s_red[1] + s_red[2] + s_red[3];
}

// bpr = mean softplus(s[:,1] - s[:,0])
__global__ void loss_kernel(const float* __restrict__ scores, float* __restrict__ out) {
    __shared__ float red[8];
    float acc = 0.f;
    for (int b = threadIdx.x; b < BATCH; b += blockDim.x) {
        float x = scores[b * 2 + 1] - scores[b * 2 + 0];
        float sp = (x > 0.f) ? x + log1pf(expf(-x)) : log1pf(expf(x));
        acc += sp;
    }
    #pragma unroll
    for (int o = 16; o; o >>= 1) acc += __shfl_down_sync(0xffffffffu, acc, o);
    if ((threadIdx.x & 31) == 0) red[threadIdx.x >> 5] = acc;
    __syncthreads();
    if (threadIdx.x == 0) {
        float s = 0.f;
        for (int i = 0; i < 8; i++) s += red[i];
        out[0] = s * (1.0f / BATCH);
    }
}

// ---------------- host ----------------

struct Scratch {
    float *y1, *repUB, *repUI, *repBI, *scores, *cval;
    int *cnt, *rowptr, *part, *ccol;
};

static void run_graph(const Scratch& S,
                      const float* fa, int na, const float* fb, int nb,
                      const int* row, const int* col, const float* val, int E,
                      float* rep) {
    int N = na + nb;
    int gN = (N + 255) / 256;
    int gE = (E + 255) / 256;
    int nblk = (N + 1023) / 1024;
    zero_int_kernel<<<gN, 256>>>(S.cnt, N);
    hist_kernel<<<gE, 256>>>(row, S.cnt, E);
    scan1_kernel<<<nblk, 256>>>(S.cnt, S.part, N);
    scan2_kernel<<<1, 256>>>(S.part, nblk);
    scan3_kernel<<<gN, 256>>>(S.cnt, S.part, S.rowptr, N, E);
    scatter_kernel<<<gE, 256>>>(row, col, val, S.cnt, S.ccol, S.cval, E);
    int gS = (N * 16 + 255) / 256;
    // layer 1: gather virtual concat(fa,fb) -> y1
    spmm_csr_kernel<false><<<gS, 256>>>(S.rowptr, S.ccol, S.cval,
                                        fa, fb, na,
                                        nullptr, nullptr, 0, nullptr, S.y1, N);
    // layer 2 + finalize: rep = (x0 + y1 + A*y1)/3
    spmm_csr_kernel<true><<<gS, 256>>>(S.rowptr, S.ccol, S.cval,
                                       S.y1, S.y1, N,
                                       fa, fb, na, S.y1, rep, N);
}

extern "C" void kernel_launch(void* const* d_in, const int* in_sizes, int n_in,
                              void* d_out, int out_size) {
    const float* users_feature   = (const float*)d_in[0];
    const float* bundles_feature = (const float*)d_in[1];
    const float* items_feature   = (const float*)d_in[2];
    const float* cw1 = (const float*)d_in[3];
    const float* cb1 = (const float*)d_in[4];
    const float* cw2 = (const float*)d_in[5];
    const float* cb2 = (const float*)d_in[6];
    const float* sw1 = (const float*)d_in[7];
    const float* sb1 = (const float*)d_in[8];
    const float* sw2 = (const float*)d_in[9];
    const float* sb2 = (const float*)d_in[10];
    const float* ub_val = (const float*)d_in[11];
    const float* ui_val = (const float*)d_in[12];
    const float* bi_val = (const float*)d_in[13];
    const int* users   = (const int*)d_in[14];
    const int* bundles = (const int*)d_in[15];
    const int* ub_row = (const int*)d_in[16];
    const int* ub_col = (const int*)d_in[17];
    const int* ui_row = (const int*)d_in[18];
    const int* ui_col = (const int*)d_in[19];
    const int* bi_row = (const int*)d_in[20];
    const int* bi_col = (const int*)d_in[21];
    const int* bundle_items = (const int*)d_in[22];

    int E_UB = in_sizes[11];
    int E_UI = in_sizes[12];
    int E_BI = in_sizes[13];

    Scratch S;
    cudaGetSymbolAddress((void**)&S.y1, g_y1);
    cudaGetSymbolAddress((void**)&S.repUB, g_repUB);
    cudaGetSymbolAddress((void**)&S.repUI, g_repUI);
    cudaGetSymbolAddress((void**)&S.repBI, g_repBI);
    cudaGetSymbolAddress((void**)&S.scores, g_scores);
    cudaGetSymbolAddress((void**)&S.cval, g_cval);
    cudaGetSymbolAddress((void**)&S.cnt, g_cnt);
    cudaGetSymbolAddress((void**)&S.rowptr, g_rowptr);
    cudaGetSymbolAddress((void**)&S.part, g_part);
    cudaGetSymbolAddress((void**)&S.ccol, g_ccol);

    run_graph(S, users_feature, NU, bundles_feature, NB, ub_row, ub_col, ub_val, E_UB, S.repUB);
    run_graph(S, users_feature, NU, items_feature,   NI, ui_row, ui_col, ui_val, E_UI, S.repUI);
    run_graph(S, bundles_feature, NB, items_feature, NI, bi_row, bi_col, bi_val, E_BI, S.repBI);

    score_kernel<<<BATCH * NCAND, 128>>>(users, bundles, bundle_items,
                                         S.repUB, S.repUI, S.repBI,
                                         cw1, cb1, cw2, cb2,
                                         sw1, sb1, sw2, sb2, S.scores);
    loss_kernel<<<1, 256>>>(S.scores, (float*)d_out);
}

// round 5
// speedup vs baseline: 2.1000x; 1.0025x over previous
#include <cuda_runtime.h>
#include <math.h>

#define D        64
#define NU       50000
#define NB       20000
#define NI       100000
#define N_UB     (NU + NB)
#define N_UI     (NU + NI)
#define N_BI     (NB + NI)
#define N_TOT    (N_UB + N_UI + N_BI)       /* 340000 */
#define OFF_UB   0
#define OFF_UI   N_UB                        /* 70000 */
#define OFF_BI   (N_UB + N_UI)               /* 220000 */
#define MAXDEG   50
#define BATCH    2048
#define NCAND    2
#define CORE_K   3
#define EMAXTOT  3000000
#define SCAN_TILE 2048
#define NPART    ((N_TOT + SCAN_TILE - 1) / SCAN_TILE)   /* 167 */

// ---------------- scratch (allocation-free rule: device globals) ----------------
__device__ float g_y1[(size_t)N_TOT * D];      // layer-1 output, all graphs
__device__ float g_repUB[(size_t)N_UB * D];
__device__ float g_repUI[(size_t)N_UI * D];
__device__ float g_repBI[(size_t)N_BI * D];
__device__ int   g_cnt[N_TOT];                 // counts -> cursor
__device__ int   g_rowptr[N_TOT + 1];
__device__ int   g_part[256];
__device__ int   g_ccol[EMAXTOT];
__device__ float g_cval[EMAXTOT];
__device__ float g_scores[BATCH * NCAND];

// ---------------- CSR build (batched over all 3 graphs) ----------------

__global__ void zero_int_kernel(int* __restrict__ p, int n) {
    int i = blockIdx.x * blockDim.x + threadIdx.x;
    if (i < n) p[i] = 0;
}

// histogram over the concatenated edge space
__global__ void hist_all_kernel(const int* __restrict__ ubr, const int* __restrict__ uir,
                                const int* __restrict__ bir,
                                int Eub, int Eui, int Ebi,
                                int* __restrict__ cnt) {
    int e = blockIdx.x * blockDim.x + threadIdx.x;
    int r;
    if (e < Eub) r = __ldg(ubr + e) + OFF_UB;
    else if (e < Eub + Eui) r = __ldg(uir + (e - Eub)) + OFF_UI;
    else if (e < Eub + Eui + Ebi) r = __ldg(bir + (e - Eub - Eui)) + OFF_BI;
    else return;
    atomicAdd(&cnt[r], 1);
}

// block-local exclusive scan over SCAN_TILE-element tiles (256 thr x 8)
__global__ void scan1_kernel(int* __restrict__ data, int* __restrict__ part, int n) {
    __shared__ int sh[256];
    int tid = threadIdx.x;
    int base = blockIdx.x * SCAN_TILE + tid * 8;
    int v[8];
    int s = 0;
    #pragma unroll
    for (int k = 0; k < 8; k++) {
        v[k] = (base + k < n) ? data[base + k] : 0;
        s += v[k];
    }
    sh[tid] = s;
    __syncthreads();
    #pragma unroll
    for (int off = 1; off < 256; off <<= 1) {
        int t = (tid >= off) ? sh[tid - off] : 0;
        __syncthreads();
        sh[tid] += t;
        __syncthreads();
    }
    if (tid == 255) part[blockIdx.x] = sh[255];
    int run = sh[tid] - s;  // exclusive within block
    #pragma unroll
    for (int k = 0; k < 8; k++) {
        if (base + k < n) data[base + k] = run;
        run += v[k];
    }
}

// each block redundantly scans part[] in smem, then:
// rowptr[i] = data[i] + partscan[i/SCAN_TILE]; data becomes cursor; rowptr[n] = E
__global__ void scan3_kernel(int* __restrict__ data, const int* __restrict__ part,
                             int* __restrict__ rowptr, int n, int np, int E) {
    __shared__ int sh[256];
    int tid = threadIdx.x;
    int s = (tid < np) ? part[tid] : 0;
    sh[tid] = s;
    __syncthreads();
    #pragma unroll
    for (int off = 1; off < 256; off <<= 1) {
        int t = (tid >= off) ? sh[tid - off] : 0;
        __syncthreads();
        sh[tid] += t;
        __syncthreads();
    }
    __syncthreads();
    // sh[k] is inclusive; exclusive = sh[k] - part[k]
    int i = blockIdx.x * blockDim.x + tid;
    if (i < n) {
        int blk = i / SCAN_TILE;
        int v = data[i] + sh[blk] - ((blk < np) ? part[blk] : 0);
        rowptr[i] = v;
        data[i] = v;   // cursor
    }
    if (i == 0) rowptr[n] = E;
}

__global__ void scatter_all_kernel(const int* __restrict__ ubr, const int* __restrict__ ubc,
                                   const float* __restrict__ ubv,
                                   const int* __restrict__ uir, const int* __restrict__ uic,
                                   const float* __restrict__ uiv,
                                   const int* __restrict__ bir, const int* __restrict__ bic,
                                   const float* __restrict__ biv,
                                   int Eub, int Eui, int Ebi,
                                   int* __restrict__ cursor,
                                   int* __restrict__ ccol, float* __restrict__ cval) {
    int e = blockIdx.x * blockDim.x + threadIdx.x;
    int r, c; float v;
    if (e < Eub) { r = __ldg(ubr + e) + OFF_UB; c = __ldg(ubc + e); v = __ldg(ubv + e); }
    else if (e < Eub + Eui) { int t = e - Eub; r = __ldg(uir + t) + OFF_UI; c = __ldg(uic + t); v = __ldg(uiv + t); }
    else if (e < Eub + Eui + Ebi) { int t = e - Eub - Eui; r = __ldg(bir + t) + OFF_BI; c = __ldg(bic + t); v = __ldg(biv + t); }
    else return;
    int p = atomicAdd(&cursor[r], 1);
    ccol[p] = c;
    cval[p] = v;
}

// ---------------- fused gather spmm over all graphs (half-warp per row) ----------------
// LAYER1: gather from per-graph virtual concat of base features -> y1 (global row r)
// LAYER2 (FIN): gather from y1's own-graph region; out = (x0 + y1[r] + acc)/3 -> per-graph rep
template <bool FIN>
__global__ void __launch_bounds__(256)
spmm_all_kernel(const int* __restrict__ rowptr, const int* __restrict__ ccol,
                const float* __restrict__ cval,
                const float* __restrict__ uf, const float* __restrict__ bf,
                const float* __restrict__ itf,
                float* __restrict__ y1,
                float* __restrict__ repUB, float* __restrict__ repUI,
                float* __restrict__ repBI) {
    int g = blockIdx.x * blockDim.x + threadIdx.x;
    int r = g >> 4;
    if (r >= N_TOT) return;
    int lane = threadIdx.x & 31;
    int sub = lane & 15;
    unsigned mask = (lane < 16) ? 0x0000FFFFu : 0xFFFF0000u;

    // per-graph selection
    const float* xa; const float* xb; int na; int off; float* rep;
    if (r < OFF_UI)      { xa = uf; xb = bf;  na = NU; off = OFF_UB; rep = repUB; }
    else if (r < OFF_BI) { xa = uf; xb = itf; na = NU; off = OFF_UI; rep = repUI; }
    else                 { xa = bf; xb = itf; na = NB; off = OFF_BI; rep = repBI; }

    const float4* ga;
    const float4* gb;
    int gna;
    if (FIN) {
        ga = reinterpret_cast<const float4*>(y1) + (size_t)off * 16;
        gb = ga;
        gna = N_TOT;   // cols always < na, single region
    } else {
        ga = reinterpret_cast<const float4*>(xa);
        gb = reinterpret_cast<const float4*>(xb);
        gna = na;
    }

    int beg = __ldg(rowptr + r), end = __ldg(rowptr + r + 1);
    float4 acc = make_float4(0.f, 0.f, 0.f, 0.f);
    for (int e0 = beg; e0 < end; e0 += 16) {
        int idx = e0 + sub;
        int c = 0; float v = 0.f;
        if (idx < end) { c = __ldg(ccol + idx); v = __ldg(cval + idx); }
        int cnt = end - e0; if (cnt > 16) cnt = 16;
        for (int j = 0; j < cnt; j++) {
            int cj = __shfl_sync(mask, c, j, 16);
            float vj = __shfl_sync(mask, v, j, 16);
            const float4* xr = (cj < gna) ? ga + (size_t)cj * 16
                                          : gb + (size_t)(cj - gna) * 16;
            float4 xv = __ldg(xr + sub);
            acc.x = fmaf(vj, xv.x, acc.x);
            acc.y = fmaf(vj, xv.y, acc.y);
            acc.z = fmaf(vj, xv.z, acc.z);
            acc.w = fmaf(vj, xv.w, acc.w);
        }
    }

    if (FIN) {
        int rl = r - off;   // row local to graph
        float4 x0 = (rl < na)
            ? __ldg(reinterpret_cast<const float4*>(xa) + (size_t)rl * 16 + sub)
            : __ldg(reinterpret_cast<const float4*>(xb) + (size_t)(rl - na) * 16 + sub);
        float4 y1v = __ldg(reinterpret_cast<const float4*>(y1) + (size_t)r * 16 + sub);
        const float s = 1.0f / 3.0f;
        acc.x = (acc.x + x0.x + y1v.x) * s;
        acc.y = (acc.y + x0.y + y1v.y) * s;
        acc.z = (acc.z + x0.z + y1v.z) * s;
        acc.w = (acc.w + x0.w + y1v.w) * s;
        reinterpret_cast<float4*>(rep)[(size_t)rl * 16 + sub] = acc;
    } else {
        reinterpret_cast<float4*>(y1)[(size_t)r * 16 + sub] = acc;
    }
}

// ---------------- scoring ----------------

__global__ void __launch_bounds__(128, 8)
score_kernel(const int* __restrict__ users, const int* __restrict__ bundles,
             const int* __restrict__ bundle_items,
             const float* __restrict__ repUB,
             const float* __restrict__ repUI,
             const float* __restrict__ repBI,
             const float* __restrict__ cw1, const float* __restrict__ cb1,
             const float* __restrict__ cw2, const float* __restrict__ cb2,
             const float* __restrict__ sw1, const float* __restrict__ sb1,
             const float* __restrict__ sw2, const float* __restrict__ sb2,
             float* __restrict__ scores) {
    __shared__ float s_u[D];
    __shared__ float s_ubu[D];
    __shared__ float s_ubb[D];
    __shared__ float s_bbi[D];
    __shared__ int   s_idx[MAXDEG];
    __shared__ float s_it[MAXDEG * 65];
    __shared__ float s_rUI[MAXDEG];
    __shared__ float s_rBI[MAXDEG];
    __shared__ float s_pi[MAXDEG];
    __shared__ float s_cw1[64];
    __shared__ float s_cb1[32];
    __shared__ float s_cw2[32];
    __shared__ float s_cb2v;
    __shared__ float s_max, s_sum, s_cnt;
    __shared__ int   s_topi[CORE_K];
    __shared__ float s_topp[CORE_K];
    __shared__ unsigned char s_fringe[MAXDEG];
    __shared__ float s_core[D], s_fr[D], s_h1[D], s_hat[D];
    __shared__ float s_red[4];

    const int pair = blockIdx.x;
    const int b = pair / NCAND;
    const int tid = threadIdx.x;
    const int user = users[b];
    const int bun  = bundles[pair];

    const float* UI_u = repUI;
    const float* UI_i = repUI + (size_t)NU * D;
    const float* UB_u = repUB;
    const float* UB_b = repUB + (size_t)NU * D;
    const float* BI_b = repBI;
    const float* BI_i = repBI + (size_t)NB * D;

    if (tid < D) {
        s_u[tid]   = UI_u[(size_t)user * D + tid];
        s_ubu[tid] = UB_u[(size_t)user * D + tid];
        s_ubb[tid] = UB_b[(size_t)bun * D + tid];
        s_bbi[tid] = BI_b[(size_t)bun * D + tid];
        s_cw1[tid] = cw1[tid];
    }
    if (tid < MAXDEG) s_idx[tid] = bundle_items[(size_t)bun * MAXDEG + tid];
    if (tid < 32) { s_cb1[tid] = cb1[tid]; s_cw2[tid] = cw2[tid]; }
    if (tid == 0) s_cb2v = cb2[0];
    __syncthreads();

    for (int i = tid; i < MAXDEG * D; i += blockDim.x) {
        int m = i >> 6, d = i & 63;
        int ci = s_idx[m];
        s_it[m * 65 + d] = (ci < NI) ? UI_i[(size_t)ci * D + d] : 0.f;
    }
    __syncthreads();

    const int w = tid >> 5, l = tid & 31;
    for (int m = w; m < MAXDEG; m += 4) {
        float a = s_it[m * 65 + l] * s_u[l] + s_it[m * 65 + 32 + l] * s_u[32 + l];
        #pragma unroll
        for (int o = 16; o; o >>= 1) a += __shfl_down_sync(0xffffffffu, a, o);
        int ci = s_idx[m];
        float bs = 0.f;
        if (ci < NI) {
            bs = BI_i[(size_t)ci * D + l] * s_bbi[l]
               + BI_i[(size_t)ci * D + 32 + l] * s_bbi[32 + l];
        }
        #pragma unroll
        for (int o = 16; o; o >>= 1) bs += __shfl_down_sync(0xffffffffu, bs, o);
        if (l == 0) { s_rUI[m] = a; s_rBI[m] = bs; }
    }
    __syncthreads();

    if (tid < MAXDEG) {
        float logit;
        if (s_idx[tid] < NI) {
            float ru = s_rUI[tid], rb = s_rBI[tid];
            float acc = s_cb2v;
            #pragma unroll
            for (int j = 0; j < 32; j++) {
                float h = fmaf(ru, s_cw1[j], fmaf(rb, s_cw1[32 + j], s_cb1[j]));
                h = fmaxf(h, 0.f);
                acc = fmaf(h, s_cw2[j], acc);
            }
            logit = acc;
        } else {
            logit = -INFINITY;
        }
        s_pi[tid] = logit;
    }
    __syncthreads();
    if (tid == 0) {
        float mx = -INFINITY;
        for (int m = 0; m < MAXDEG; m++) mx = fmaxf(mx, s_pi[m]);
        s_max = mx;
    }
    __syncthreads();
    if (tid < MAXDEG) s_pi[tid] = expf(s_pi[tid] - s_max);
    __syncthreads();
    if (tid == 0) {
        float sum = 0.f;
        for (int m = 0; m < MAXDEG; m++) sum += s_pi[m];
        s_sum = sum;
    }
    __syncthreads();
    if (tid < MAXDEG) s_pi[tid] /= s_sum;
    __syncthreads();

    if (tid == 0) {
        bool taken[MAXDEG];
        for (int m = 0; m < MAXDEG; m++) taken[m] = false;
        float tsum = 0.f;
        #pragma unroll
        for (int k = 0; k < CORE_K; k++) {
            float best = -1.f; int bi = 0;
            for (int m = 0; m < MAXDEG; m++)
                if (!taken[m] && s_pi[m] > best) { best = s_pi[m]; bi = m; }
            taken[bi] = true;
            s_topi[k] = bi;
            s_topp[k] = best;
            tsum += best;
        }
        tsum += 1e-10f;
        #pragma unroll
        for (int k = 0; k < CORE_K; k++) s_topp[k] /= tsum;
        int cnt = 0;
        for (int m = 0; m < MAXDEG; m++) {
            unsigned char fr = (s_idx[m] < NI && !taken[m]) ? 1 : 0;
            s_fringe[m] = fr;
            cnt += fr;
        }
        s_cnt = fmaxf((float)cnt, 1.0f);
    }
    __syncthreads();

    if (tid < D) {
        float hc = 0.f;
        #pragma unroll
        for (int k = 0; k < CORE_K; k++)
            hc = fmaf(s_it[s_topi[k] * 65 + tid], s_topp[k], hc);
        float fs = 0.f;
        for (int m = 0; m < MAXDEG; m++)
            if (s_fringe[m]) fs += s_it[m * 65 + tid];
        s_core[tid] = hc;
        s_fr[tid] = fs / s_cnt;
    }
    __syncthreads();

    if (tid < D) {
        float acc = sb1[tid];
        #pragma unroll 8
        for (int i = 0; i < D; i++) acc = fmaf(s_core[i], sw1[i * D + tid], acc);
        #pragma unroll 8
        for (int i = 0; i < D; i++) acc = fmaf(s_fr[i], sw1[(D + i) * D + tid], acc);
        s_h1[tid] = fmaxf(acc, 0.f);
    }
    __syncthreads();
    if (tid < D) {
        float acc = sb2[tid];
        #pragma unroll 8
        for (int j = 0; j < D; j++) acc = fmaf(s_h1[j], sw2[j * D + tid], acc);
        s_hat[tid] = s_core[tid] + acc;
    }
    __syncthreads();

    float part = 0.f;
    if (tid < D) part = s_u[tid] * s_ubb[tid] + s_ubu[tid] * s_hat[tid];
    #pragma unroll
    for (int o = 16; o; o >>= 1) part += __shfl_down_sync(0xffffffffu, part, o);
    if (l == 0) s_red[w] = part;
    __syncthreads();
    if (tid == 0) scores[pair] = s_red[0] + s_red[1] + s_red[2] + s_red[3];
}

__global__ void loss_kernel(const float* __restrict__ scores, float* __restrict__ out) {
    __shared__ float red[8];
    float acc = 0.f;
    for (int b = threadIdx.x; b < BATCH; b += blockDim.x) {
        float x = scores[b * 2 + 1] - scores[b * 2 + 0];
        float sp = (x > 0.f) ? x + log1pf(expf(-x)) : log1pf(expf(x));
        acc += sp;
    }
    #pragma unroll
    for (int o = 16; o; o >>= 1) acc += __shfl_down_sync(0xffffffffu, acc, o);
    if ((threadIdx.x & 31) == 0) red[threadIdx.x >> 5] = acc;
    __syncthreads();
    if (threadIdx.x == 0) {
        float s = 0.f;
        for (int i = 0; i < 8; i++) s += red[i];
        out[0] = s * (1.0f / BATCH);
    }
}

// ---------------- host ----------------

extern "C" void kernel_launch(void* const* d_in, const int* in_sizes, int n_in,
                              void* d_out, int out_size) {
    const float* uf  = (const float*)d_in[0];
    const float* bf  = (const float*)d_in[1];
    const float* itf = (const float*)d_in[2];
    const float* cw1 = (const float*)d_in[3];
    const float* cb1 = (const float*)d_in[4];
    const float* cw2 = (const float*)d_in[5];
    const float* cb2 = (const float*)d_in[6];
    const float* sw1 = (const float*)d_in[7];
    const float* sb1 = (const float*)d_in[8];
    const float* sw2 = (const float*)d_in[9];
    const float* sb2 = (const float*)d_in[10];
    const float* ub_val = (const float*)d_in[11];
    const float* ui_val = (const float*)d_in[12];
    const float* bi_val = (const float*)d_in[13];
    const int* users   = (const int*)d_in[14];
    const int* bundles = (const int*)d_in[15];
    const int* ub_row = (const int*)d_in[16];
    const int* ub_col = (const int*)d_in[17];
    const int* ui_row = (const int*)d_in[18];
    const int* ui_col = (const int*)d_in[19];
    const int* bi_row = (const int*)d_in[20];
    const int* bi_col = (const int*)d_in[21];
    const int* bundle_items = (const int*)d_in[22];

    int Eub = in_sizes[11];
    int Eui = in_sizes[12];
    int Ebi = in_sizes[13];
    int Etot = Eub + Eui + Ebi;

    float *y1, *repUB, *repUI, *repBI, *scores, *cval;
    int *cnt, *rowptr, *part, *ccol;
    cudaGetSymbolAddress((void**)&y1, g_y1);
    cudaGetSymbolAddress((void**)&repUB, g_repUB);
    cudaGetSymbolAddress((void**)&repUI, g_repUI);
    cudaGetSymbolAddress((void**)&repBI, g_repBI);
    cudaGetSymbolAddress((void**)&scores, g_scores);
    cudaGetSymbolAddress((void**)&cval, g_cval);
    cudaGetSymbolAddress((void**)&cnt, g_cnt);
    cudaGetSymbolAddress((void**)&rowptr, g_rowptr);
    cudaGetSymbolAddress((void**)&part, g_part);
    cudaGetSymbolAddress((void**)&ccol, g_ccol);

    int gN = (N_TOT + 255) / 256;
    int gE = (Etot + 255) / 256;
    int nblk = (N_TOT + SCAN_TILE - 1) / SCAN_TILE;

    zero_int_kernel<<<gN, 256>>>(cnt, N_TOT);
    hist_all_kernel<<<gE, 256>>>(ub_row, ui_row, bi_row, Eub, Eui, Ebi, cnt);
    scan1_kernel<<<nblk, 256>>>(cnt, part, N_TOT);
    scan3_kernel<<<gN, 256>>>(cnt, part, rowptr, N_TOT, nblk, Etot);
    scatter_all_kernel<<<gE, 256>>>(ub_row, ub_col, ub_val,
                                    ui_row, ui_col, ui_val,
                                    bi_row, bi_col, bi_val,
                                    Eub, Eui, Ebi, cnt, ccol, cval);

    int gS = (N_TOT * 16 + 255) / 256;
    spmm_all_kernel<false><<<gS, 256>>>(rowptr, ccol, cval, uf, bf, itf,
                                        y1, repUB, repUI, repBI);
    spmm_all_kernel<true><<<gS, 256>>>(rowptr, ccol, cval, uf, bf, itf,
                                       y1, repUB, repUI, repBI);

    score_kernel<<<BATCH * NCAND, 128>>>(users, bundles, bundle_items,
                                         repUB, repUI, repBI,
                                         cw1, cb1, cw2, cb2,
                                         sw1, sb1, sw2, sb2, scores);
    loss_kernel<<<1, 256>>>(scores, (float*)d_out);
}